// round 4
// baseline (speedup 1.0000x reference)
#include <cuda_runtime.h>
#include <cuda_bf16.h>
#include <math.h>

// ---------------------------------------------------------------------------
// Problem constants
// ---------------------------------------------------------------------------
#define BATCH 16
#define SEQL  128
#define IN_DIM 1218
#define HID 200          // H
#define G4  800          // 4*H
#define LSTMD 400
#define SMAX 8001        // (L-1)(L-2)/2
#define ML (BATCH*SEQL)  // 2048
#define OUT_BASE (BATCH*SMAX*LSTMD)  // 51,206,400

// ---------------------------------------------------------------------------
// Scratch (static device globals -- no runtime allocation).
// IMPORTANT: these are referenced ONLY inside device code. Passing them as
// host-side kernel arguments passes the host shadow address (silently read
// as zeros via ATS on GB300) -- that was the round-2/3 bug.
// ---------------------------------------------------------------------------
__device__ float g_emb[ML * IN_DIM];        // (b*L+t, 1218)
__device__ float g_gx [2 * ML * G4];        // [dir][b][t][800]  (reused both layers)
__device__ float g_h0 [ML * LSTMD];         // layer0 output [b][t][400]
__device__ float g_h1 [ML * LSTMD];         // layer1 output
__device__ float g_hx [2 * 32 * 208];       // h exchange [parity][pair][<=208]
__device__ int   g_bar[32];                 // per-group step barrier counters
__device__ int   g_lens[BATCH];
__device__ int   g_ij  [BATCH * SMAX];

// ---------------------------------------------------------------------------
// lens[b] = #(word_idxs != PAD)
// ---------------------------------------------------------------------------
__global__ void lens_kernel(const int* __restrict__ wi)
{
    int b = blockIdx.x, t = threadIdx.x;
    int v = (wi[b * SEQL + t] != 0) ? 1 : 0;
    int cnt = __syncthreads_count(v);
    if (t == 0) g_lens[b] = cnt;
}

// ---------------------------------------------------------------------------
// Zero the per-group barrier counters (before each recurrence launch)
// ---------------------------------------------------------------------------
__global__ void zero_bar_kernel()
{
    if (threadIdx.x < 32) g_bar[threadIdx.x] = 0;
}

// ---------------------------------------------------------------------------
// Embedding concat
// ---------------------------------------------------------------------------
__global__ void embed_kernel(const float* __restrict__ ext_emb,
                             const float* __restrict__ word_emb,
                             const float* __restrict__ pos_emb,
                             const float* __restrict__ dep_emb,
                             const float* __restrict__ ent_emb,
                             const float* __restrict__ iob_emb,
                             const float* __restrict__ bert,
                             const int* __restrict__ word_idxs,
                             const int* __restrict__ pos_idxs,
                             const int* __restrict__ dep_idxs,
                             const int* __restrict__ ent_idxs,
                             const int* __restrict__ iob_idxs)
{
    long idx = (long)blockIdx.x * blockDim.x + threadIdx.x;
    if (idx >= (long)ML * IN_DIM) return;
    int d  = (int)(idx % IN_DIM);
    int bt = (int)(idx / IN_DIM);
    float v;
    if (d < 300) {
        int wi  = word_idxs[bt];
        int wid = (wi >= 20000) ? 1 : wi;
        v = ext_emb[(size_t)wi * 300 + d] + word_emb[(size_t)wid * 300 + d];
    } else if (d < 350) {
        v = pos_emb[pos_idxs[bt] * 50 + (d - 300)];
    } else if (d < 400) {
        v = dep_emb[dep_idxs[bt] * 50 + (d - 350)];
    } else if (d < 425) {
        v = ent_emb[ent_idxs[bt] * 25 + (d - 400)];
    } else if (d < 450) {
        v = iob_emb[iob_idxs[bt] * 25 + (d - 425)];
    } else {
        v = bert[(size_t)bt * 768 + (d - 450)];
    }
    g_emb[idx] = v;
}

// ---------------------------------------------------------------------------
// Input-projection GEMM:  C[dir][m][n] = A[m][:] . W[dir][n][:] + bih + bhh
// A selected INSIDE the kernel: src_sel==0 -> g_emb, else -> g_h0.
// W: per dir N x K row-major.  grid.z = dir.
// Tiles: 128x64, BK=16, 256 threads, 8x4 microtile. C -> g_gx.
// ---------------------------------------------------------------------------
__global__ void __launch_bounds__(256)
gemm_bias_kernel(const float* __restrict__ Wall,
                 const float* __restrict__ bih_all, const float* __restrict__ bhh_all,
                 int M, int N, int K, int src_sel)
{
    const float* A = src_sel ? g_h0 : g_emb;
    const int dir = blockIdx.z;
    const float* W  = Wall + (size_t)dir * N * K;
    const float* bi = bih_all + dir * N;
    const float* bh = bhh_all + dir * N;
    float* C = g_gx + (size_t)dir * M * N;

    __shared__ float As[16][128];
    __shared__ float Bs[16][64];

    const int m0 = blockIdx.y * 128;
    const int n0 = blockIdx.x * 64;
    const int tid = threadIdx.x;
    const int tx = tid & 15;
    const int ty = tid >> 4;

    float acc[8][4];
#pragma unroll
    for (int i = 0; i < 8; i++)
#pragma unroll
        for (int j = 0; j < 4; j++) acc[i][j] = 0.f;

    for (int k0 = 0; k0 < K; k0 += 16) {
        // A tile: 128 rows x 16 cols
#pragma unroll
        for (int u = 0; u < 2; u++) {
            int f   = tid + u * 256;          // 0..511 quad slot
            int row = f >> 2;
            int kq  = (f & 3) * 4;
            const float* ap = A + (size_t)(m0 + row) * K + k0 + kq;
#pragma unroll
            for (int c = 0; c < 4; c++) {
                int kk = k0 + kq + c;
                As[kq + c][row] = (kk < K) ? ap[c] : 0.f;
            }
        }
        // B tile: 64 rows x 16 cols
        {
            int f   = tid;
            int row = f >> 2;
            int kq  = (f & 3) * 4;
            int n   = n0 + row;
            const float* wp = W + (size_t)n * K + k0 + kq;
#pragma unroll
            for (int c = 0; c < 4; c++) {
                int kk = k0 + kq + c;
                Bs[kq + c][row] = (n < N && kk < K) ? wp[c] : 0.f;
            }
        }
        __syncthreads();
#pragma unroll
        for (int k = 0; k < 16; k++) {
            float a[8], bb[4];
#pragma unroll
            for (int i = 0; i < 8; i++) a[i] = As[k][ty * 8 + i];
#pragma unroll
            for (int j = 0; j < 4; j++) bb[j] = Bs[k][tx * 4 + j];
#pragma unroll
            for (int i = 0; i < 8; i++)
#pragma unroll
                for (int j = 0; j < 4; j++) acc[i][j] += a[i] * bb[j];
        }
        __syncthreads();
    }
#pragma unroll
    for (int i = 0; i < 8; i++) {
        int m = m0 + ty * 8 + i;
#pragma unroll
        for (int j = 0; j < 4; j++) {
            int n = n0 + tx * 4 + j;
            if (n < N) C[(size_t)m * N + n] = acc[i][j] + bi[n] + bh[n];
        }
    }
}

// ---------------------------------------------------------------------------
// Recurrence. 128 CTAs = 32 groups of 4; group = (dir,b) pair, rank r in
// group owns hidden indices [r*50, r*50+50), i.e. gate rows {q*200+r*50+jj}.
// W_hh slice lives in registers (50 float4 per thread, 200 active threads).
// h exchanged through L2 (__stcg/__ldcg, double buffered) + per-group
// monotonic atomic-counter barrier once per step.
// All 128 CTAs are wave-1 resident (<=148 SMs), so the spin is safe.
// ---------------------------------------------------------------------------
__global__ void __launch_bounds__(224, 1)
recur_kernel(const float* __restrict__ Whh,   // [2][800][200]
             int layer_sel)
{
    const int r    = blockIdx.x & 3;    // rank in group 0..3
    const int pair = blockIdx.x >> 2;   // 0..31
    const int dir  = pair >> 4;
    const int b    = pair & 15;
    const int tid  = threadIdx.x;
    const int len  = g_lens[b];
    float* outh = layer_sel ? g_h1 : g_h0;

    __shared__ float4 hs4[50];
    float* hs = (float*)hs4;
    __shared__ float dots[200];

    // Load W_hh slice into registers
    float4 W4[50];
    int grow = 0;
    if (tid < 200) {
        int q = tid / 50, jj = tid % 50;
        grow = q * 200 + r * 50 + jj;
        const float4* wp = (const float4*)(Whh + ((size_t)dir * G4 + grow) * HID);
#pragma unroll
        for (int kk = 0; kk < 50; kk++) W4[kk] = wp[kk];
    }
    if (tid < 50) hs4[tid] = make_float4(0.f, 0.f, 0.f, 0.f);
    float c = 0.f;
    const float* gxb = g_gx + ((size_t)dir * BATCH + b) * SEQL * G4;
    __syncthreads();

    for (int t = 0; t < SEQL; t++) {
        const int tp = dir ? (SEQL - 1 - t) : t;
        const float mt = (tp < len) ? 1.f : 0.f;

        if (tid < 200) {
            float gval = gxb[(size_t)tp * G4 + grow];
            float a0 = 0.f, a1 = 0.f, a2 = 0.f, a3 = 0.f;
#pragma unroll
            for (int kk = 0; kk < 50; kk++) {
                float4 hv = hs4[kk];
                a0 += W4[kk].x * hv.x;
                a1 += W4[kk].y * hv.y;
                a2 += W4[kk].z * hv.z;
                a3 += W4[kk].w * hv.w;
            }
            dots[tid] = (a0 + a1) + (a2 + a3) + gval;
        }
        __syncthreads();

        if (tid < 50) {
            float gi = dots[tid];
            float gf = dots[50 + tid];
            float gg = dots[100 + tid];
            float go = dots[150 + tid];
            float si = 1.f / (1.f + __expf(-gi));
            float sf = 1.f / (1.f + __expf(-gf));
            float so = 1.f / (1.f + __expf(-go));
            float cn = sf * c + si * tanhf(gg);
            float hn = so * tanhf(cn);
            float hp = hs[r * 50 + tid];
            float hnew = mt * hn + (1.f - mt) * hp;
            c = mt * cn + (1.f - mt) * c;
            outh[((size_t)b * SEQL + tp) * LSTMD + dir * HID + r * 50 + tid] = mt * hn;
            __stcg(g_hx + ((size_t)(t & 1) * 32 + pair) * 208 + r * 50 + tid, hnew);
        }
        __threadfence();
        __syncthreads();

        // per-group barrier: monotonic counter, 4 arrivals per step
        if (tid == 0) {
            atomicAdd(&g_bar[pair], 1);
            int target = 4 * (t + 1);
            volatile int* p = &g_bar[pair];
            while (*p < target) { }
            __threadfence();
        }
        __syncthreads();

        if (tid < 200)
            hs[tid] = __ldcg(g_hx + ((size_t)(t & 1) * 32 + pair) * 208 + tid);
        __syncthreads();
    }
}

// ---------------------------------------------------------------------------
// s -> (i,j) table. Valid pairs for batch b: 0 <= i < j < n,  n = lens[b]-1,
// ordered lexicographically (i major).  Also writes the lens-2 output tail.
// ---------------------------------------------------------------------------
__global__ void ij_kernel(float* __restrict__ out, int extra)
{
    int idx = blockIdx.x * blockDim.x + threadIdx.x;
    if (idx < extra && idx < BATCH)
        out[(size_t)OUT_BASE + idx] = (float)(g_lens[idx] - 2);
    if (idx >= BATCH * SMAX) return;
    int s = idx % SMAX;
    int b = idx / SMAX;
    int n = g_lens[b] - 1;
    int cnt = n * (n - 1) / 2;
    int val = 0;
    if (s < cnt) {
        float fn = (float)(2 * n - 1);
        int i = (int)floorf((fn - sqrtf(fn * fn - 8.0f * (float)s)) * 0.5f);
        if (i < 0) i = 0;
        if (i > n - 2) i = n - 2;
        // cum(i) = i*(2n-1-i)/2 ; fix up float error
        while ((i + 1) * (2 * n - 2 - i) / 2 <= s) i++;
        while (i > 0 && i * (2 * n - 1 - i) / 2 > s) i--;
        int j = i + 1 + (s - i * (2 * n - 1 - i) / 2);
        val = (i << 8) | j;
    }
    g_ij[idx] = val;
}

// ---------------------------------------------------------------------------
// Span emit:  out[b][s][d]  (float4 granularity)
//   d<200 : h1[b][j][d]   - h1[b][i][d]        (forward half)
//   d>=200: h1[b][i+1][d] - h1[b][j+1][d]      (backward half)
// invalid s -> 0
// ---------------------------------------------------------------------------
__global__ void span_kernel(float* __restrict__ out)
{
    long idx = (long)blockIdx.x * blockDim.x + threadIdx.x; // over 16*8001*100
    if (idx >= (long)BATCH * SMAX * 100) return;
    int d4 = (int)(idx % 100);
    int bs = (int)(idx / 100);
    int s = bs % SMAX;
    int b = bs / SMAX;
    int n = g_lens[b] - 1;
    int cnt = n * (n - 1) / 2;
    float4 v = make_float4(0.f, 0.f, 0.f, 0.f);
    if (s < cnt) {
        int p = g_ij[bs];
        int i = p >> 8;
        int j = p & 255;
        const float4* hb = (const float4*)(g_h1 + (size_t)b * SEQL * LSTMD);
        float4 x, y;
        if (d4 < 50) {
            x = hb[j * 100 + d4];
            y = hb[i * 100 + d4];
        } else {
            x = hb[(i + 1) * 100 + d4];
            y = hb[(j + 1) * 100 + d4];
        }
        v.x = x.x - y.x; v.y = x.y - y.y; v.z = x.z - y.z; v.w = x.w - y.w;
    }
    ((float4*)out)[idx] = v;
}

// ---------------------------------------------------------------------------
// Launch
// ---------------------------------------------------------------------------
extern "C" void kernel_launch(void* const* d_in, const int* in_sizes, int n_in,
                              void* d_out, int out_size)
{
    const float* ext_emb  = (const float*)d_in[0];
    const float* word_emb = (const float*)d_in[1];
    const float* pos_emb  = (const float*)d_in[2];
    const float* dep_emb  = (const float*)d_in[3];
    const float* ent_emb  = (const float*)d_in[4];
    const float* iob_emb  = (const float*)d_in[5];
    const float* w_ih_l0  = (const float*)d_in[6];
    const float* w_hh_l0  = (const float*)d_in[7];
    const float* b_ih_l0  = (const float*)d_in[8];
    const float* b_hh_l0  = (const float*)d_in[9];
    const float* w_ih_l1  = (const float*)d_in[10];
    const float* w_hh_l1  = (const float*)d_in[11];
    const float* b_ih_l1  = (const float*)d_in[12];
    const float* b_hh_l1  = (const float*)d_in[13];
    const float* bert     = (const float*)d_in[14];
    const int* word_idxs  = (const int*)d_in[15];
    const int* pos_idxs   = (const int*)d_in[16];
    const int* dep_idxs   = (const int*)d_in[17];
    const int* ent_idxs   = (const int*)d_in[18];
    const int* iob_idxs   = (const int*)d_in[19];
    float* out = (float*)d_out;

    // 1. lengths
    lens_kernel<<<BATCH, SEQL>>>(word_idxs);

    // 2. embedding concat
    {
        long tot = (long)ML * IN_DIM;
        int blocks = (int)((tot + 255) / 256);
        embed_kernel<<<blocks, 256>>>(ext_emb, word_emb, pos_emb, dep_emb,
                                      ent_emb, iob_emb, bert,
                                      word_idxs, pos_idxs, dep_idxs,
                                      ent_idxs, iob_idxs);
    }

    // 3. layer0 input projection  (M=2048, N=800, K=1218), A = g_emb
    {
        dim3 grid((G4 + 63) / 64, ML / 128, 2);
        gemm_bias_kernel<<<grid, 256>>>(w_ih_l0, b_ih_l0, b_hh_l0,
                                        ML, G4, IN_DIM, 0);
    }

    // 4. layer0 recurrence
    zero_bar_kernel<<<1, 32>>>();
    recur_kernel<<<128, 224>>>(w_hh_l0, 0);

    // 5. layer1 input projection (M=2048, N=800, K=400), A = g_h0
    {
        dim3 grid((G4 + 63) / 64, ML / 128, 2);
        gemm_bias_kernel<<<grid, 256>>>(w_ih_l1, b_ih_l1, b_hh_l1,
                                        ML, G4, LSTMD, 1);
    }

    // 6. layer1 recurrence
    zero_bar_kernel<<<1, 32>>>();
    recur_kernel<<<128, 224>>>(w_hh_l1, 1);

    // 7. s -> (i,j) table (+ lens-2 tail if present)
    {
        int extra = out_size - OUT_BASE;
        if (extra < 0) extra = 0;
        int tot = BATCH * SMAX;
        ij_kernel<<<(tot + 255) / 256, 256>>>(out, extra);
    }

    // 8. span emit
    {
        long tot = (long)BATCH * SMAX * 100;
        int blocks = (int)((tot + 255) / 256);
        span_kernel<<<blocks, 256>>>(out);
    }
}

// round 5
// speedup vs baseline: 1.1530x; 1.1530x over previous
#include <cuda_runtime.h>
#include <cuda_bf16.h>
#include <math.h>
#include <stdint.h>

// ---------------------------------------------------------------------------
// Problem constants
// ---------------------------------------------------------------------------
#define BATCH 16
#define SEQL  128
#define IN_DIM 1218
#define HID 200          // H
#define G4  800          // 4*H
#define LSTMD 400
#define SMAX 8001        // (L-1)(L-2)/2
#define ML (BATCH*SEQL)  // 2048
#define OUT_BASE (BATCH*SMAX*LSTMD)  // 51,206,400

// ---------------------------------------------------------------------------
// Scratch (static device globals -- no runtime allocation).
// IMPORTANT: referenced ONLY inside device code. Passing these as host-side
// kernel arguments passes the host shadow address (silently reads zeros via
// ATS on GB300) -- that was the round-2/3 bug.
// ---------------------------------------------------------------------------
__device__ float g_emb[ML * IN_DIM];        // (b*L+t, 1218)
__device__ float g_gx [2 * ML * G4];        // [dir][b][t][800]  (reused both layers)
__device__ float g_h0 [ML * LSTMD];         // layer0 output [b][t][400]
__device__ float g_h1 [ML * LSTMD];         // layer1 output
__device__ float g_hx [2 * 32 * 208];       // h exchange [parity][pair][<=208]
__device__ int   g_bar[32];                 // per-group step barrier counters
__device__ int   g_lens[BATCH];
__device__ int   g_ij  [BATCH * SMAX];

// ---------------------------------------------------------------------------
// lens[b] = #(word_idxs != PAD).  Block 0 also zeroes the barrier counters
// (runs before any recurrence launch in the same stream; replay-safe).
// ---------------------------------------------------------------------------
__global__ void lens_kernel(const int* __restrict__ wi)
{
    int b = blockIdx.x, t = threadIdx.x;
    if (b == 0 && t < 32) g_bar[t] = 0;
    int v = (wi[b * SEQL + t] != 0) ? 1 : 0;
    int cnt = __syncthreads_count(v);
    if (t == 0) g_lens[b] = cnt;
}

// ---------------------------------------------------------------------------
// Embedding concat
// ---------------------------------------------------------------------------
__global__ void embed_kernel(const float* __restrict__ ext_emb,
                             const float* __restrict__ word_emb,
                             const float* __restrict__ pos_emb,
                             const float* __restrict__ dep_emb,
                             const float* __restrict__ ent_emb,
                             const float* __restrict__ iob_emb,
                             const float* __restrict__ bert,
                             const int* __restrict__ word_idxs,
                             const int* __restrict__ pos_idxs,
                             const int* __restrict__ dep_idxs,
                             const int* __restrict__ ent_idxs,
                             const int* __restrict__ iob_idxs)
{
    long idx = (long)blockIdx.x * blockDim.x + threadIdx.x;
    if (idx >= (long)ML * IN_DIM) return;
    int d  = (int)(idx % IN_DIM);
    int bt = (int)(idx / IN_DIM);
    float v;
    if (d < 300) {
        int wi  = word_idxs[bt];
        int wid = (wi >= 20000) ? 1 : wi;
        v = ext_emb[(size_t)wi * 300 + d] + word_emb[(size_t)wid * 300 + d];
    } else if (d < 350) {
        v = pos_emb[pos_idxs[bt] * 50 + (d - 300)];
    } else if (d < 400) {
        v = dep_emb[dep_idxs[bt] * 50 + (d - 350)];
    } else if (d < 425) {
        v = ent_emb[ent_idxs[bt] * 25 + (d - 400)];
    } else if (d < 450) {
        v = iob_emb[iob_idxs[bt] * 25 + (d - 425)];
    } else {
        v = bert[(size_t)bt * 768 + (d - 450)];
    }
    g_emb[idx] = v;
}

// ---------------------------------------------------------------------------
// tf32 tensor-core GEMM:  C[dir][m][n] = A[m][:] . W[dir][n][:] + bih + bhh
// A selected inside kernel: src_sel==0 -> g_emb, else -> g_h0.
// mma.sync.m16n8k8 tf32. CTA tile 128x64, BK=16, 8 warps (4m x 2n),
// warp tile 32x32 (2 m-tiles x 4 n-tiles). Double-buffered smem.
// Smem strides 136/72: fragment LDS bank = (8k+idx)%32 -> conflict-free.
// ---------------------------------------------------------------------------
#define BM 128
#define BN 64
#define BK 16
#define ASTR 136
#define BSTR 72

__device__ __forceinline__ uint32_t f2tf32(float v)
{
    uint32_t r;
    asm("cvt.rna.tf32.f32 %0, %1;" : "=r"(r) : "f"(v));
    return r;
}

__global__ void __launch_bounds__(256)
gemm_tf32_kernel(const float* __restrict__ Wall,
                 const float* __restrict__ bih_all, const float* __restrict__ bhh_all,
                 int M, int N, int K, int src_sel)
{
    const float* A = src_sel ? g_h0 : g_emb;
    const int dir = blockIdx.z;
    const float* W  = Wall + (size_t)dir * N * K;
    const float* bi = bih_all + dir * N;
    const float* bh = bhh_all + dir * N;
    float* C = g_gx + (size_t)dir * M * N;

    __shared__ uint32_t As[2][BK][ASTR];
    __shared__ uint32_t Bs[2][BK][BSTR];

    const int tid  = threadIdx.x;
    const int m0   = blockIdx.y * BM;
    const int n0   = blockIdx.x * BN;
    const int warp = tid >> 5;
    const int lane = tid & 31;
    const int wm   = warp & 3;       // 0..3
    const int wn   = warp >> 2;      // 0..1
    const int gid  = lane >> 2;      // 0..7
    const int tig  = lane & 3;       // 0..3

    // fill indices
    const int arow = tid >> 2;          // 0..63 (and +64)
    const int akq  = (tid & 3) * 4;     // 0,4,8,12

    float acc[2][4][4];
#pragma unroll
    for (int mi = 0; mi < 2; mi++)
#pragma unroll
        for (int ni = 0; ni < 4; ni++)
#pragma unroll
            for (int r = 0; r < 4; r++) acc[mi][ni][r] = 0.f;

    const int numk = (K + BK - 1) / BK;

    float aR[8], bR[4];

    // prefetch stage 0
    {
        const int k0 = 0;
#pragma unroll
        for (int u = 0; u < 2; u++) {
            int m = m0 + arow + u * 64;
            const float* ap = A + (size_t)m * K + k0 + akq;
#pragma unroll
            for (int c = 0; c < 4; c++) {
                int kk = k0 + akq + c;
                aR[u * 4 + c] = (kk < K) ? ap[c] : 0.f;
            }
        }
        int n = n0 + arow;
        const float* wp = W + (size_t)n * K + k0 + akq;
#pragma unroll
        for (int c = 0; c < 4; c++) {
            int kk = k0 + akq + c;
            bR[c] = (n < N && kk < K) ? wp[c] : 0.f;
        }
    }

    for (int s = 0; s < numk; s++) {
        const int buf = s & 1;
        // STS (with tf32 rounding)
#pragma unroll
        for (int u = 0; u < 2; u++)
#pragma unroll
            for (int c = 0; c < 4; c++)
                As[buf][akq + c][arow + u * 64] = f2tf32(aR[u * 4 + c]);
#pragma unroll
        for (int c = 0; c < 4; c++)
            Bs[buf][akq + c][arow] = f2tf32(bR[c]);
        __syncthreads();

        // prefetch next stage
        if (s + 1 < numk) {
            const int k0 = (s + 1) * BK;
#pragma unroll
            for (int u = 0; u < 2; u++) {
                int m = m0 + arow + u * 64;
                const float* ap = A + (size_t)m * K + k0 + akq;
#pragma unroll
                for (int c = 0; c < 4; c++) {
                    int kk = k0 + akq + c;
                    aR[u * 4 + c] = (kk < K) ? ap[c] : 0.f;
                }
            }
            int n = n0 + arow;
            const float* wp = W + (size_t)n * K + k0 + akq;
#pragma unroll
            for (int c = 0; c < 4; c++) {
                int kk = k0 + akq + c;
                bR[c] = (n < N && kk < K) ? wp[c] : 0.f;
            }
        }

        // compute 2 k8 steps
#pragma unroll
        for (int kk = 0; kk < 2; kk++) {
            const int kb = kk * 8;
            uint32_t af[2][4];
#pragma unroll
            for (int mi = 0; mi < 2; mi++) {
                int m = wm * 32 + mi * 16 + gid;
                af[mi][0] = As[buf][kb + tig][m];
                af[mi][1] = As[buf][kb + tig][m + 8];
                af[mi][2] = As[buf][kb + tig + 4][m];
                af[mi][3] = As[buf][kb + tig + 4][m + 8];
            }
#pragma unroll
            for (int ni = 0; ni < 4; ni++) {
                int n = wn * 32 + ni * 8 + gid;
                uint32_t b0 = Bs[buf][kb + tig][n];
                uint32_t b1 = Bs[buf][kb + tig + 4][n];
#pragma unroll
                for (int mi = 0; mi < 2; mi++) {
                    asm volatile(
                        "mma.sync.aligned.m16n8k8.row.col.f32.tf32.tf32.f32 "
                        "{%0,%1,%2,%3},{%4,%5,%6,%7},{%8,%9},{%0,%1,%2,%3};"
                        : "+f"(acc[mi][ni][0]), "+f"(acc[mi][ni][1]),
                          "+f"(acc[mi][ni][2]), "+f"(acc[mi][ni][3])
                        : "r"(af[mi][0]), "r"(af[mi][1]),
                          "r"(af[mi][2]), "r"(af[mi][3]),
                          "r"(b0), "r"(b1));
                }
            }
        }
        __syncthreads();
    }

    // epilogue
#pragma unroll
    for (int mi = 0; mi < 2; mi++) {
#pragma unroll
        for (int ni = 0; ni < 4; ni++) {
            int m = m0 + wm * 32 + mi * 16 + gid;
            int n = n0 + wn * 32 + ni * 8 + tig * 2;
            if (n < N) {
                float bs0 = bi[n] + bh[n];
                float bs1 = bi[n + 1] + bh[n + 1];
                float2 v0 = make_float2(acc[mi][ni][0] + bs0, acc[mi][ni][1] + bs1);
                float2 v1 = make_float2(acc[mi][ni][2] + bs0, acc[mi][ni][3] + bs1);
                *(float2*)&C[(size_t)m * N + n] = v0;
                *(float2*)&C[(size_t)(m + 8) * N + n] = v1;
            }
        }
    }
}

// ---------------------------------------------------------------------------
// Recurrence. 128 CTAs = 32 groups of 4; group = (dir,b) pair, rank r in
// group owns hidden indices [r*50, r*50+50), i.e. gate rows {q*200+r*50+jj}.
// W_hh slice lives in registers (50 float4 per thread, 200 active threads).
// h exchanged through L2 (__stcg/__ldcg, double buffered) + per-group
// monotonic atomic-counter barrier once per step (base offset per layer so
// counters are zeroed only once per launch sequence, in lens_kernel).
// All 128 CTAs are wave-1 resident, so the spin is safe.
// ---------------------------------------------------------------------------
__global__ void __launch_bounds__(224, 1)
recur_kernel(const float* __restrict__ Whh,   // [2][800][200]
             int layer_sel)
{
    const int r    = blockIdx.x & 3;    // rank in group 0..3
    const int pair = blockIdx.x >> 2;   // 0..31
    const int dir  = pair >> 4;
    const int b    = pair & 15;
    const int tid  = threadIdx.x;
    const int len  = g_lens[b];
    const int tbase = layer_sel ? 512 : 0;   // monotonic counter base
    float* outh = layer_sel ? g_h1 : g_h0;

    __shared__ float4 hs4[50];
    float* hs = (float*)hs4;
    __shared__ float dots[200];

    // Load W_hh slice into registers
    float4 W4[50];
    int grow = 0;
    if (tid < 200) {
        int q = tid / 50, jj = tid % 50;
        grow = q * 200 + r * 50 + jj;
        const float4* wp = (const float4*)(Whh + ((size_t)dir * G4 + grow) * HID);
#pragma unroll
        for (int kk = 0; kk < 50; kk++) W4[kk] = wp[kk];
    }
    if (tid < 50) hs4[tid] = make_float4(0.f, 0.f, 0.f, 0.f);
    float c = 0.f;
    const float* gxb = g_gx + ((size_t)dir * BATCH + b) * SEQL * G4;
    __syncthreads();

    for (int t = 0; t < SEQL; t++) {
        const int tp = dir ? (SEQL - 1 - t) : t;
        const float mt = (tp < len) ? 1.f : 0.f;

        if (tid < 200) {
            float gval = gxb[(size_t)tp * G4 + grow];
            float a0 = 0.f, a1 = 0.f, a2 = 0.f, a3 = 0.f;
#pragma unroll
            for (int kk = 0; kk < 50; kk++) {
                float4 hv = hs4[kk];
                a0 += W4[kk].x * hv.x;
                a1 += W4[kk].y * hv.y;
                a2 += W4[kk].z * hv.z;
                a3 += W4[kk].w * hv.w;
            }
            dots[tid] = (a0 + a1) + (a2 + a3) + gval;
        }
        __syncthreads();

        if (tid < 50) {
            float gi = dots[tid];
            float gf = dots[50 + tid];
            float gg = dots[100 + tid];
            float go = dots[150 + tid];
            float si = 1.f / (1.f + __expf(-gi));
            float sf = 1.f / (1.f + __expf(-gf));
            float so = 1.f / (1.f + __expf(-go));
            float cn = sf * c + si * tanhf(gg);
            float hn = so * tanhf(cn);
            float hp = hs[r * 50 + tid];
            float hnew = mt * hn + (1.f - mt) * hp;
            c = mt * cn + (1.f - mt) * c;
            outh[((size_t)b * SEQL + tp) * LSTMD + dir * HID + r * 50 + tid] = mt * hn;
            __stcg(g_hx + ((size_t)(t & 1) * 32 + pair) * 208 + r * 50 + tid, hnew);
        }
        __threadfence();
        __syncthreads();

        // per-group barrier: monotonic counter, 4 arrivals per step
        if (tid == 0) {
            atomicAdd(&g_bar[pair], 1);
            int target = tbase + 4 * (t + 1);
            volatile int* p = &g_bar[pair];
            while (*p < target) { }
            __threadfence();
        }
        __syncthreads();

        if (tid < 200)
            hs[tid] = __ldcg(g_hx + ((size_t)(t & 1) * 32 + pair) * 208 + tid);
        __syncthreads();
    }
}

// ---------------------------------------------------------------------------
// s -> (i,j) table. Valid pairs for batch b: 0 <= i < j < n,  n = lens[b]-1,
// ordered lexicographically (i major).  Also writes the lens-2 output tail.
// ---------------------------------------------------------------------------
__global__ void ij_kernel(float* __restrict__ out, int extra)
{
    int idx = blockIdx.x * blockDim.x + threadIdx.x;
    if (idx < extra && idx < BATCH)
        out[(size_t)OUT_BASE + idx] = (float)(g_lens[idx] - 2);
    if (idx >= BATCH * SMAX) return;
    int s = idx % SMAX;
    int b = idx / SMAX;
    int n = g_lens[b] - 1;
    int cnt = n * (n - 1) / 2;
    int val = 0;
    if (s < cnt) {
        float fn = (float)(2 * n - 1);
        int i = (int)floorf((fn - sqrtf(fn * fn - 8.0f * (float)s)) * 0.5f);
        if (i < 0) i = 0;
        if (i > n - 2) i = n - 2;
        // cum(i) = i*(2n-1-i)/2 ; fix up float error
        while ((i + 1) * (2 * n - 2 - i) / 2 <= s) i++;
        while (i > 0 && i * (2 * n - 1 - i) / 2 > s) i--;
        int j = i + 1 + (s - i * (2 * n - 1 - i) / 2);
        val = (i << 8) | j;
    }
    g_ij[idx] = val;
}

// ---------------------------------------------------------------------------
// Span emit:  out[b][s][d]  (float4 granularity)
//   d<200 : h1[b][j][d]   - h1[b][i][d]        (forward half)
//   d>=200: h1[b][i+1][d] - h1[b][j+1][d]      (backward half)
// invalid s -> 0
// ---------------------------------------------------------------------------
__global__ void span_kernel(float* __restrict__ out)
{
    long idx = (long)blockIdx.x * blockDim.x + threadIdx.x; // over 16*8001*100
    if (idx >= (long)BATCH * SMAX * 100) return;
    int d4 = (int)(idx % 100);
    int bs = (int)(idx / 100);
    int s = bs % SMAX;
    int b = bs / SMAX;
    int n = g_lens[b] - 1;
    int cnt = n * (n - 1) / 2;
    float4 v = make_float4(0.f, 0.f, 0.f, 0.f);
    if (s < cnt) {
        int p = g_ij[bs];
        int i = p >> 8;
        int j = p & 255;
        const float4* hb = (const float4*)(g_h1 + (size_t)b * SEQL * LSTMD);
        float4 x, y;
        if (d4 < 50) {
            x = hb[j * 100 + d4];
            y = hb[i * 100 + d4];
        } else {
            x = hb[(i + 1) * 100 + d4];
            y = hb[(j + 1) * 100 + d4];
        }
        v.x = x.x - y.x; v.y = x.y - y.y; v.z = x.z - y.z; v.w = x.w - y.w;
    }
    ((float4*)out)[idx] = v;
}

// ---------------------------------------------------------------------------
// Launch
// ---------------------------------------------------------------------------
extern "C" void kernel_launch(void* const* d_in, const int* in_sizes, int n_in,
                              void* d_out, int out_size)
{
    const float* ext_emb  = (const float*)d_in[0];
    const float* word_emb = (const float*)d_in[1];
    const float* pos_emb  = (const float*)d_in[2];
    const float* dep_emb  = (const float*)d_in[3];
    const float* ent_emb  = (const float*)d_in[4];
    const float* iob_emb  = (const float*)d_in[5];
    const float* w_ih_l0  = (const float*)d_in[6];
    const float* w_hh_l0  = (const float*)d_in[7];
    const float* b_ih_l0  = (const float*)d_in[8];
    const float* b_hh_l0  = (const float*)d_in[9];
    const float* w_ih_l1  = (const float*)d_in[10];
    const float* w_hh_l1  = (const float*)d_in[11];
    const float* b_ih_l1  = (const float*)d_in[12];
    const float* b_hh_l1  = (const float*)d_in[13];
    const float* bert     = (const float*)d_in[14];
    const int* word_idxs  = (const int*)d_in[15];
    const int* pos_idxs   = (const int*)d_in[16];
    const int* dep_idxs   = (const int*)d_in[17];
    const int* ent_idxs   = (const int*)d_in[18];
    const int* iob_idxs   = (const int*)d_in[19];
    float* out = (float*)d_out;

    // 1. lengths + barrier-counter reset
    lens_kernel<<<BATCH, SEQL>>>(word_idxs);

    // 2. embedding concat
    {
        long tot = (long)ML * IN_DIM;
        int blocks = (int)((tot + 255) / 256);
        embed_kernel<<<blocks, 256>>>(ext_emb, word_emb, pos_emb, dep_emb,
                                      ent_emb, iob_emb, bert,
                                      word_idxs, pos_idxs, dep_idxs,
                                      ent_idxs, iob_idxs);
    }

    // 3. layer0 input projection  (M=2048, N=800, K=1218), A = g_emb
    {
        dim3 grid((G4 + BN - 1) / BN, ML / BM, 2);
        gemm_tf32_kernel<<<grid, 256>>>(w_ih_l0, b_ih_l0, b_hh_l0,
                                        ML, G4, IN_DIM, 0);
    }

    // 4. layer0 recurrence
    recur_kernel<<<128, 224>>>(w_hh_l0, 0);

    // 5. layer1 input projection (M=2048, N=800, K=400), A = g_h0
    {
        dim3 grid((G4 + BN - 1) / BN, ML / BM, 2);
        gemm_tf32_kernel<<<grid, 256>>>(w_ih_l1, b_ih_l1, b_hh_l1,
                                        ML, G4, LSTMD, 1);
    }

    // 6. layer1 recurrence
    recur_kernel<<<128, 224>>>(w_hh_l1, 1);

    // 7. s -> (i,j) table (+ lens-2 tail if present)
    {
        int extra = out_size - OUT_BASE;
        if (extra < 0) extra = 0;
        int tot = BATCH * SMAX;
        ij_kernel<<<(tot + 255) / 256, 256>>>(out, extra);
    }

    // 8. span emit
    {
        long tot = (long)BATCH * SMAX * 100;
        int blocks = (int)((tot + 255) / 256);
        span_kernel<<<blocks, 256>>>(out);
    }
}